// round 1
// baseline (speedup 1.0000x reference)
#include <cuda_runtime.h>

#define TOKS    2048
#define NNODES  1024
#define FEAT    128
#define NBLK    64
#define CHUNK   (TOKS / NBLK)     // 32 tokens per block
#define THREADS 256
#define QUADS   (FEAT / 4)        // 32 float4 lanes per token row

// Scratch (device globals: no allocations allowed).
// g_diff is zero at process start (static init) and re-zeroed by each launch's
// scan phase, so every call sees a clean difference array.
__device__ float  g_diff[TOKS * FEAT];
__device__ float4 g_partial[NBLK * QUADS];
__device__ volatile int g_flagA;   // scatter done count
__device__ volatile int g_flagB;   // chunk partials published count
__device__ int          g_flagC;   // partials consumed count (for reset)

__device__ __forceinline__ float4 f4add(float4 a, float4 b) {
    return make_float4(a.x + b.x, a.y + b.y, a.z + b.z, a.w + b.w);
}

__global__ __launch_bounds__(THREADS, 1)
void span_encoder_kernel(const int* __restrict__ starts,
                         const int* __restrict__ ends,
                         const float* __restrict__ embed,
                         float* __restrict__ out)
{
    __shared__ float4 sdata[CHUNK][QUADS];   // 16 KB: this block's diff chunk
    __shared__ float4 sred[8][QUADS];        //  4 KB: per-slice (4-token) sums
    __shared__ float4 scarry[QUADS];         // carry-in from preceding chunks

    const int c   = blockIdx.x;
    const int tid = threadIdx.x;
    const float4 zero4 = make_float4(0.f, 0.f, 0.f, 0.f);

    // ---------------- Phase 1: scatter +/- embed into difference array ----
    {
        const int nodesPerBlk = NNODES / NBLK;        // 16
        const int nodeBase    = c * nodesPerBlk;
        #pragma unroll
        for (int rep = 0; rep < nodesPerBlk * FEAT / THREADS; ++rep) {   // 8
            int idx = rep * THREADS + tid;            // 0..2047
            int n   = nodeBase + (idx >> 7);
            int f   = idx & (FEAT - 1);
            int s   = __ldg(&starts[n]);
            int e   = __ldg(&ends[n]);
            if (s <= e) {                              // non-empty span
                float v = __ldg(&embed[n * FEAT + f]);
                atomicAdd(&g_diff[s * FEAT + f], v);
                if (e + 1 < TOKS)                      // row TOKS never read
                    atomicAdd(&g_diff[(e + 1) * FEAT + f], -v);
            }
        }
    }
    __threadfence();
    __syncthreads();
    if (tid == 0) {
        atomicAdd((int*)&g_flagA, 1);
        while (g_flagA < NBLK) { }                     // all blocks resident
    }
    __syncthreads();

    // ---------------- Phase 2: load own chunk into smem, re-zero diff -----
    {
        float4* diff4 = (float4*)g_diff;               // [TOKS][QUADS]
        const int base4 = c * CHUNK * QUADS;
        #pragma unroll
        for (int it = 0; it < (CHUNK * QUADS) / THREADS; ++it) {  // 4
            int j = it * THREADS + tid;
            float4 v = __ldcg(&diff4[base4 + j]);      // atomics landed in L2
            sdata[j >> 5][j & 31] = v;
            __stcg(&diff4[base4 + j], zero4);          // clean for next replay
        }
    }
    __syncthreads();

    // ---------------- Phase 3: per-chunk feature sums, publish ------------
    {
        int q = tid & 31;
        int s = tid >> 5;                              // 0..7, 4 tokens each
        float4 acc =       sdata[s * 4 + 0][q];
        acc = f4add(acc,   sdata[s * 4 + 1][q]);
        acc = f4add(acc,   sdata[s * 4 + 2][q]);
        acc = f4add(acc,   sdata[s * 4 + 3][q]);
        sred[s][q] = acc;
    }
    __syncthreads();
    if (tid < QUADS) {
        float4 acc = sred[0][tid];
        #pragma unroll
        for (int s = 1; s < 8; ++s) acc = f4add(acc, sred[s][tid]);
        __stcg(&g_partial[c * QUADS + tid], acc);
        __threadfence();
    }
    __syncthreads();
    if (tid == 0) {
        atomicAdd((int*)&g_flagB, 1);
        while (g_flagB < NBLK) { }
    }
    __syncthreads();

    // ---------------- Phase 4: carry = sum of preceding chunk partials ----
    if (tid < QUADS) {
        float4 a0 = zero4, a1 = zero4;
        int cc = 0;
        for (; cc + 1 < c; cc += 2) {
            a0 = f4add(a0, __ldcg(&g_partial[(cc    ) * QUADS + tid]));
            a1 = f4add(a1, __ldcg(&g_partial[(cc + 1) * QUADS + tid]));
        }
        if (cc < c)
            a0 = f4add(a0, __ldcg(&g_partial[cc * QUADS + tid]));
        scarry[tid] = f4add(a0, a1);
    }
    __syncthreads();
    // Flag reset: the last block to consume the partials resets all flags.
    // Every block increments C only AFTER it passed spin-B and read partials,
    // so resetting B/A here cannot strand a spinner.
    if (tid == 0) {
        int r = atomicAdd(&g_flagC, 1);
        if (r == NBLK - 1) {
            g_flagC = 0;
            g_flagA = 0;
            g_flagB = 0;
            __threadfence();
        }
    }

    // ---------------- Phase 5: hierarchical scan within chunk, write out --
    // Slice-level carry from sred (computed in phase 3), so all 8 warps work.
    {
        int q = tid & 31;
        int s = tid >> 5;
        float4 acc = scarry[q];
        #pragma unroll
        for (int sp = 0; sp < 7; ++sp)
            if (sp < s) acc = f4add(acc, sred[sp][q]);
        float4* out4 = (float4*)out;
        const int t0 = c * CHUNK + s * 4;
        #pragma unroll
        for (int k = 0; k < 4; ++k) {
            acc = f4add(acc, sdata[s * 4 + k][q]);
            out4[(t0 + k) * QUADS + q] = acc;
        }
    }
}

extern "C" void kernel_launch(void* const* d_in, const int* in_sizes, int n_in,
                              void* d_out, int out_size) {
    const int*   starts = (const int*)d_in[0];
    const int*   ends   = (const int*)d_in[1];
    const float* embed  = (const float*)d_in[2];
    float*       out    = (float*)d_out;
    (void)in_sizes; (void)n_in; (void)out_size;
    span_encoder_kernel<<<NBLK, THREADS>>>(starts, ends, embed, out);
}

// round 2
// speedup vs baseline: 1.3810x; 1.3810x over previous
#include <cuda_runtime.h>

#define TOKS    2048
#define NNODES  1024
#define FEAT    128
#define QUADS   32                 // FEAT/4 float4 lanes per token row
#define NBLK    64
#define CHUNK   32                 // TOKS / NBLK
#define THREADS 256

__device__ __forceinline__ float4 f4add(float4 a, float4 b) {
    return make_float4(a.x + b.x, a.y + b.y, a.z + b.z, a.w + b.w);
}

__global__ __launch_bounds__(THREADS, 1)
void span_encoder_kernel(const int4* __restrict__ starts4,
                         const int4* __restrict__ ends4,
                         const float4* __restrict__ embed4,
                         float4* __restrict__ out4)
{
    __shared__ int    s_full[NNODES];        // nodes fully covering this chunk
    __shared__ int    s_part[NNODES];        // packed n|lo|hi partial overlaps
    __shared__ int    s_nfull, s_npart;
    __shared__ float4 sdiff[CHUNK][QUADS];   // 16 KB local difference array
    __shared__ float4 gacc[8][QUADS];        // per-group full-cover accums
    __shared__ float4 sred[8][QUADS];        // per-4-token-slice sums
    __shared__ float4 sfull[QUADS];          // combined full-cover sum

    const int tid = threadIdx.x;
    const int c0  = blockIdx.x * CHUNK;
    const float4 zero4 = make_float4(0.f, 0.f, 0.f, 0.f);

    if (tid == 0) { s_nfull = 0; s_npart = 0; }
    #pragma unroll
    for (int i = 0; i < (CHUNK * QUADS) / THREADS; ++i) {    // 4
        int j = i * THREADS + tid;
        sdiff[j >> 5][j & 31] = zero4;
    }
    __syncthreads();

    // ---- Classify all 1024 nodes against this chunk (4 nodes/thread) ----
    {
        int4 sv = __ldg(&starts4[tid]);
        int4 ev = __ldg(&ends4[tid]);
        int ss[4] = {sv.x, sv.y, sv.z, sv.w};
        int ee[4] = {ev.x, ev.y, ev.z, ev.w};
        #pragma unroll
        for (int k = 0; k < 4; ++k) {
            int n  = tid * 4 + k;
            int lo = ss[k] - c0;     if (lo < 0)     lo = 0;
            int hi = ee[k] - c0 + 1; if (hi > CHUNK) hi = CHUNK;
            if (lo < hi) {                       // overlaps (also implies s<=e)
                if (lo == 0 && hi == CHUNK) {
                    s_full[atomicAdd(&s_nfull, 1)] = n;
                } else {
                    s_part[atomicAdd(&s_npart, 1)] = (n << 12) | (lo << 6) | hi;
                }
            }
        }
    }
    __syncthreads();

    const int q = tid & 31;          // float4 lane within feature row
    const int g = tid >> 5;          // warp-group 0..7
    const int nfull = s_nfull;
    const int npart = s_npart;

    // ---- Full-cover nodes: chunk-constant contribution (2-deep MLP) -----
    {
        float4 a0 = zero4, a1 = zero4;
        int i = g;
        for (; i + 8 < nfull; i += 16) {
            int n0 = s_full[i];
            int n1 = s_full[i + 8];
            a0 = f4add(a0, __ldg(&embed4[n0 * QUADS + q]));
            a1 = f4add(a1, __ldg(&embed4[n1 * QUADS + q]));
        }
        if (i < nfull)
            a0 = f4add(a0, __ldg(&embed4[s_full[i] * QUADS + q]));
        gacc[g][q] = f4add(a0, a1);
    }

    // ---- Partial nodes: +/- into local difference array (rare) ----------
    for (int i = g; i < npart; i += 8) {
        int pk = s_part[i];
        int n  = pk >> 12;
        int lo = (pk >> 6) & 63;
        int hi = pk & 63;
        float4 v = __ldg(&embed4[n * QUADS + q]);
        float* d = &sdiff[lo][q].x;
        atomicAdd(d + 0, v.x);
        atomicAdd(d + 1, v.y);
        atomicAdd(d + 2, v.z);
        atomicAdd(d + 3, v.w);
        if (hi < CHUNK) {
            float* d2 = &sdiff[hi][q].x;
            atomicAdd(d2 + 0, -v.x);
            atomicAdd(d2 + 1, -v.y);
            atomicAdd(d2 + 2, -v.z);
            atomicAdd(d2 + 3, -v.w);
        }
    }
    __syncthreads();

    // ---- Combine group accumulators; per-slice sums ---------------------
    if (tid < QUADS) {
        float4 a = gacc[0][tid];
        #pragma unroll
        for (int gg = 1; gg < 8; ++gg) a = f4add(a, gacc[gg][tid]);
        sfull[tid] = a;
    }
    {
        float4 a =       sdiff[g * 4 + 0][q];
        a = f4add(a,     sdiff[g * 4 + 1][q]);
        a = f4add(a,     sdiff[g * 4 + 2][q]);
        a = f4add(a,     sdiff[g * 4 + 3][q]);
        sred[g][q] = a;
    }
    __syncthreads();

    // ---- Hierarchical local scan + write out ----------------------------
    {
        float4 acc = sfull[q];
        #pragma unroll
        for (int sp = 0; sp < 7; ++sp)
            if (sp < g) acc = f4add(acc, sred[sp][q]);
        const int t0 = c0 + g * 4;
        #pragma unroll
        for (int k = 0; k < 4; ++k) {
            acc = f4add(acc, sdiff[g * 4 + k][q]);
            out4[(t0 + k) * QUADS + q] = acc;
        }
    }
}

extern "C" void kernel_launch(void* const* d_in, const int* in_sizes, int n_in,
                              void* d_out, int out_size) {
    const int4*   starts = (const int4*)d_in[0];
    const int4*   ends   = (const int4*)d_in[1];
    const float4* embed  = (const float4*)d_in[2];
    float4*       out    = (float4*)d_out;
    (void)in_sizes; (void)n_in; (void)out_size;
    span_encoder_kernel<<<NBLK, THREADS>>>(starts, ends, embed, out);
}

// round 3
// speedup vs baseline: 1.4410x; 1.0435x over previous
#include <cuda_runtime.h>

#define TOKS    2048
#define NNODES  1024
#define FEAT    128
#define QUADS   32                 // FEAT/4 float4 lanes per token row
#define NBLK    64
#define CHUNK   32                 // TOKS / NBLK
#define THREADS 512
#define NGRP    16                 // THREADS/32 warps (node-parallel groups)

__device__ __forceinline__ float4 f4add(float4 a, float4 b) {
    return make_float4(a.x + b.x, a.y + b.y, a.z + b.z, a.w + b.w);
}

__global__ __launch_bounds__(THREADS, 1)
void span_encoder_kernel(const int* __restrict__ starts,
                         const int* __restrict__ ends,
                         const float4* __restrict__ embed4,
                         float4* __restrict__ out4)
{
    __shared__ int    s_full[NNODES];        // nodes fully covering this chunk
    __shared__ int    s_part[NNODES];        // packed n|lo|hi partial overlaps
    __shared__ int    s_nfull, s_npart;
    __shared__ float4 sdiff[CHUNK][QUADS];   // 16 KB local difference array
    __shared__ float4 gacc[NGRP][QUADS];     // per-group full-cover accums
    __shared__ float4 sred[NGRP][QUADS];     // per-2-token-slice sums
    __shared__ float4 sfull[QUADS];          // combined full-cover sum

    const int tid  = threadIdx.x;
    const int lane = tid & 31;
    const int g    = tid >> 5;               // warp id 0..15
    const int c0   = blockIdx.x * CHUNK;
    const unsigned lt_mask = (1u << lane) - 1u;
    const float4 zero4 = make_float4(0.f, 0.f, 0.f, 0.f);

    if (tid == 0) { s_nfull = 0; s_npart = 0; }
    #pragma unroll
    for (int i = 0; i < (CHUNK * QUADS) / THREADS; ++i) {    // 2
        int j = i * THREADS + tid;
        sdiff[j >> 5][j & 31] = zero4;
    }
    __syncthreads();

    // ---- Classify all nodes vs this chunk: warp-ballot compaction -------
    #pragma unroll
    for (int r = 0; r < NNODES / THREADS; ++r) {             // 2 rounds
        int n  = r * THREADS + tid;
        int s  = __ldg(&starts[n]);
        int e  = __ldg(&ends[n]);
        int lo = s - c0;     if (lo < 0)     lo = 0;
        int hi = e - c0 + 1; if (hi > CHUNK) hi = CHUNK;
        bool ov     = (lo < hi);
        bool isFull = ov && (lo == 0) && (hi == CHUNK);
        bool isPart = ov && !isFull;

        unsigned mf = __ballot_sync(0xffffffffu, isFull);
        unsigned mp = __ballot_sync(0xffffffffu, isPart);
        int baseF = 0, baseP = 0;
        if (lane == 0) {
            if (mf) baseF = atomicAdd(&s_nfull, __popc(mf));
            if (mp) baseP = atomicAdd(&s_npart, __popc(mp));
        }
        baseF = __shfl_sync(0xffffffffu, baseF, 0);
        baseP = __shfl_sync(0xffffffffu, baseP, 0);
        if (isFull) s_full[baseF + __popc(mf & lt_mask)] = n;
        if (isPart) s_part[baseP + __popc(mp & lt_mask)] = (n << 12) | (lo << 6) | hi;
    }
    __syncthreads();

    const int q     = lane;                  // quad within feature row
    const int nfull = s_nfull;
    const int npart = s_npart;

    // ---- Full-cover nodes: chunk-constant contribution, MLP=4 -----------
    {
        float4 a0 = zero4, a1 = zero4, a2 = zero4, a3 = zero4;
        int i = g;
        for (; i + 3 * NGRP < nfull; i += 4 * NGRP) {
            int n0 = s_full[i];
            int n1 = s_full[i +     NGRP];
            int n2 = s_full[i + 2 * NGRP];
            int n3 = s_full[i + 3 * NGRP];
            a0 = f4add(a0, __ldg(&embed4[n0 * QUADS + q]));
            a1 = f4add(a1, __ldg(&embed4[n1 * QUADS + q]));
            a2 = f4add(a2, __ldg(&embed4[n2 * QUADS + q]));
            a3 = f4add(a3, __ldg(&embed4[n3 * QUADS + q]));
        }
        for (; i < nfull; i += NGRP)
            a0 = f4add(a0, __ldg(&embed4[s_full[i] * QUADS + q]));
        gacc[g][q] = f4add(f4add(a0, a1), f4add(a2, a3));
    }

    // ---- Partial nodes: +/- into local difference array (rare) ----------
    for (int i = g; i < npart; i += NGRP) {
        int pk = s_part[i];
        int n  = pk >> 12;
        int lo = (pk >> 6) & 63;
        int hi = pk & 63;
        float4 v = __ldg(&embed4[n * QUADS + q]);
        float* d = &sdiff[lo][q].x;
        atomicAdd(d + 0, v.x);
        atomicAdd(d + 1, v.y);
        atomicAdd(d + 2, v.z);
        atomicAdd(d + 3, v.w);
        if (hi < CHUNK) {
            float* d2 = &sdiff[hi][q].x;
            atomicAdd(d2 + 0, -v.x);
            atomicAdd(d2 + 1, -v.y);
            atomicAdd(d2 + 2, -v.z);
            atomicAdd(d2 + 3, -v.w);
        }
    }
    __syncthreads();

    // ---- Combine group accumulators; per-slice (2-token) sums -----------
    if (tid < QUADS) {
        float4 a = gacc[0][tid];
        #pragma unroll
        for (int gg = 1; gg < NGRP; ++gg) a = f4add(a, gacc[gg][tid]);
        sfull[tid] = a;
    }
    sred[g][q] = f4add(sdiff[g * 2 + 0][q], sdiff[g * 2 + 1][q]);
    __syncthreads();

    // ---- Hierarchical local scan + write out ----------------------------
    {
        float4 acc = sfull[q];
        #pragma unroll
        for (int sp = 0; sp < NGRP - 1; ++sp)
            if (sp < g) acc = f4add(acc, sred[sp][q]);
        const int t0 = c0 + g * 2;
        #pragma unroll
        for (int k = 0; k < 2; ++k) {
            acc = f4add(acc, sdiff[g * 2 + k][q]);
            out4[(t0 + k) * QUADS + q] = acc;
        }
    }
}

extern "C" void kernel_launch(void* const* d_in, const int* in_sizes, int n_in,
                              void* d_out, int out_size) {
    const int*    starts = (const int*)d_in[0];
    const int*    ends   = (const int*)d_in[1];
    const float4* embed  = (const float4*)d_in[2];
    float4*       out    = (float4*)d_out;
    (void)in_sizes; (void)n_in; (void)out_size;
    span_encoder_kernel<<<NBLK, THREADS>>>(starts, ends, embed, out);
}